// round 8
// baseline (speedup 1.0000x reference)
#include <cuda_runtime.h>
#include <cuda_fp16.h>
#include <math.h>
#include <stdint.h>

#define IN_DIM   128
#define OUT_DIM  128
#define CAP_N    100000
#define CAP_E    1600000
#define ALPHA    0.2f
#define EPS_GAT  9e-15f
#define SCAN_TILE 1024
#define MAX_SCAN_BLOCKS 1024

// ---------------- scratch (static __device__, zero-initialized) ---------------
__device__ __half g_h[CAP_N * OUT_DIM];    // 25.6 MB, fp16 h for gathers
__device__ float g_s[CAP_N];
__device__ float g_t[CAP_N];
__device__ int   g_deg[CAP_N];             // zero at load; re-zeroed by k_agg
__device__ int   g_rowptr[CAP_N + 1];
__device__ int   g_cursor[CAP_N];
__device__ int2  g_pair[CAP_E];            // CSR payload: {dst*32, t[dst] bits}
__device__ int   g_bsum[MAX_SCAN_BLOCKS];

// ---------------- helpers ------------------------------------------------------
__device__ __forceinline__ uint32_t smem_u32(const void* p) {
    uint32_t a;
    asm("{ .reg .u64 t; cvta.to.shared.u64 t, %1; cvt.u32.u64 %0, t; }"
        : "=r"(a) : "l"(p));
    return a;
}
__device__ __forceinline__ int probe_is64(const void* ei, int N, int* s_flag) {
    if (threadIdx.x < 32) {
        long long v = ((const long long*)ei)[threadIdx.x];
        int bad = (v < 0 || v >= (long long)N) ? 1 : 0;
        unsigned m = __ballot_sync(0xFFFFFFFFu, bad);
        if (threadIdx.x == 0) *s_flag = (m == 0);
    }
    __syncthreads();
    return *s_flag;
}

// ---------------- K1: mma.sync GEMM: h = x @ W (fp16 in, fp32 acc) ------------
#define XS 136
#define SM_XS   0
#define SM_WS   34816
#define SM_ATTN 69632
#define SM_TOT  70656

__global__ void __launch_bounds__(256)
k_gemm_mma(const float* __restrict__ x, const float* __restrict__ W,
           const float* __restrict__ attn, int N) {
    extern __shared__ char sm[];
    __half* xs = (__half*)(sm + SM_XS);
    __half* ws = (__half*)(sm + SM_WS);
    float* s_attn = (float*)(sm + SM_ATTN);

    const int tid = threadIdx.x;
    const int wid = tid >> 5;
    const int lane = tid & 31;
    const int row0 = blockIdx.x * 128;

    s_attn[tid] = attn[tid];

    #pragma unroll
    for (int it = 0; it < 16; it++) {
        int idx = it * 256 + tid;
        int r = idx >> 5, c4 = (idx & 31) * 4;
        int gr = row0 + r;
        float4 v = make_float4(0.f, 0.f, 0.f, 0.f);
        if (gr < N) v = ((const float4*)x)[(long long)gr * 32 + (idx & 31)];
        __half2 h0 = __float22half2_rn(make_float2(v.x, v.y));
        __half2 h1 = __float22half2_rn(make_float2(v.z, v.w));
        *(uint2*)&xs[r * XS + c4] = make_uint2(*(unsigned*)&h0, *(unsigned*)&h1);
    }
    #pragma unroll
    for (int it = 0; it < 16; it++) {
        int idx = it * 256 + tid;
        int k = idx >> 5, c4 = (idx & 31) * 4;
        float4 v = ((const float4*)W)[idx];
        __half2 h0 = __float22half2_rn(make_float2(v.x, v.y));
        __half2 h1 = __float22half2_rn(make_float2(v.z, v.w));
        *(uint2*)&ws[k * XS + c4] = make_uint2(*(unsigned*)&h0, *(unsigned*)&h1);
    }
    __syncthreads();

    const uint32_t xs_b = smem_u32(xs);
    const uint32_t ws_b = smem_u32(ws);
    const int r0 = wid * 16;
    const int rl = r0 + (lane >> 2);
    const int rh = rl + 8;
    float p_lo = 0.f, q_lo = 0.f, p_hi = 0.f, q_hi = 0.f;

    #pragma unroll
    for (int half = 0; half < 2; half++) {
        float c[8][4];
        #pragma unroll
        for (int t = 0; t < 8; t++)
            c[t][0] = c[t][1] = c[t][2] = c[t][3] = 0.f;

        #pragma unroll
        for (int k0 = 0; k0 < 8; k0++) {
            int k = k0 * 16;
            int g = lane >> 3;
            int arow = r0 + (lane & 7) + (g & 1) * 8;
            int acol = k + (g >> 1) * 8;
            uint32_t aaddr = xs_b + (arow * XS + acol) * 2;
            uint32_t a0, a1, a2, a3;
            asm volatile("ldmatrix.sync.aligned.m8n8.x4.shared.b16 {%0,%1,%2,%3}, [%4];"
                         : "=r"(a0), "=r"(a1), "=r"(a2), "=r"(a3) : "r"(aaddr));
            #pragma unroll
            for (int t = 0; t < 8; t++) {
                int n0 = half * 64 + t * 8;
                int brow = k + (lane & 15);
                uint32_t baddr = ws_b + (brow * XS + n0) * 2;
                uint32_t b0, b1;
                asm volatile("ldmatrix.sync.aligned.m8n8.x2.trans.shared.b16 {%0,%1}, [%2];"
                             : "=r"(b0), "=r"(b1) : "r"(baddr));
                asm volatile(
                    "mma.sync.aligned.m16n8k16.row.col.f32.f16.f16.f32 "
                    "{%0,%1,%2,%3}, {%4,%5,%6,%7}, {%8,%9}, {%0,%1,%2,%3};"
                    : "+f"(c[t][0]), "+f"(c[t][1]), "+f"(c[t][2]), "+f"(c[t][3])
                    : "r"(a0), "r"(a1), "r"(a2), "r"(a3), "r"(b0), "r"(b1));
            }
        }
        #pragma unroll
        for (int t = 0; t < 8; t++) {
            int col0 = half * 64 + t * 8 + (lane & 3) * 2;
            float as0 = s_attn[col0], as1 = s_attn[col0 + 1];
            float ad0 = s_attn[128 + col0], ad1 = s_attn[128 + col0 + 1];
            p_lo = fmaf(c[t][0], as0, fmaf(c[t][1], as1, p_lo));
            q_lo = fmaf(c[t][0], ad0, fmaf(c[t][1], ad1, q_lo));
            p_hi = fmaf(c[t][2], as0, fmaf(c[t][3], as1, p_hi));
            q_hi = fmaf(c[t][2], ad0, fmaf(c[t][3], ad1, q_hi));
            __half2 hl = __float22half2_rn(make_float2(c[t][0], c[t][1]));
            __half2 hh = __float22half2_rn(make_float2(c[t][2], c[t][3]));
            if (row0 + rl < N) *(__half2*)&g_h[(long long)(row0 + rl) * 128 + col0] = hl;
            if (row0 + rh < N) *(__half2*)&g_h[(long long)(row0 + rh) * 128 + col0] = hh;
        }
    }
    #pragma unroll
    for (int o = 1; o <= 2; o <<= 1) {
        p_lo += __shfl_xor_sync(0xFFFFFFFFu, p_lo, o);
        q_lo += __shfl_xor_sync(0xFFFFFFFFu, q_lo, o);
        p_hi += __shfl_xor_sync(0xFFFFFFFFu, p_hi, o);
        q_hi += __shfl_xor_sync(0xFFFFFFFFu, q_hi, o);
    }
    if ((lane & 3) == 0) {
        if (row0 + rl < N) { g_s[row0 + rl] = p_lo; g_t[row0 + rl] = q_lo; }
        if (row0 + rh < N) { g_s[row0 + rh] = p_hi; g_t[row0 + rh] = q_hi; }
    }
}

// ---------------- K2: histogram of src (2 edges/thread, vector loads) ----------
__global__ void k_hist(const void* __restrict__ ei, int E, int N) {
    __shared__ int s_is64;
    int is64 = probe_is64(ei, N, &s_is64);
    int e0 = (blockIdx.x * blockDim.x + threadIdx.x) * 2;
    if (e0 >= E) return;
    if (is64) {
        const long long* p = (const long long*)ei;
        if (e0 + 1 < E) {
            longlong2 v = *(const longlong2*)&p[e0];
            atomicAdd(&g_deg[(int)v.x], 1);
            atomicAdd(&g_deg[(int)v.y], 1);
        } else {
            atomicAdd(&g_deg[(int)p[e0]], 1);
        }
    } else {
        const int* p = (const int*)ei;
        if (e0 + 1 < E) {
            int2 v = *(const int2*)&p[e0];
            atomicAdd(&g_deg[v.x], 1);
            atomicAdd(&g_deg[v.y], 1);
        } else {
            atomicAdd(&g_deg[p[e0]], 1);
        }
    }
}

// ---------------- K3a: per-block reduce of deg ---------------------------------
__global__ void k_scan1(int N) {
    int t = threadIdx.x;
    int base = blockIdx.x * SCAN_TILE + t * 4;
    int s = 0;
    if (base + 3 < N) {
        int4 d = *(const int4*)&g_deg[base];
        s = d.x + d.y + d.z + d.w;
    } else {
        for (int k = 0; k < 4; k++)
            if (base + k < N) s += g_deg[base + k];
    }
    int lane = t & 31, wid = t >> 5;
    #pragma unroll
    for (int o = 16; o > 0; o >>= 1)
        s += __shfl_xor_sync(0xFFFFFFFFu, s, o);
    __shared__ int ws[8];
    if (lane == 0) ws[wid] = s;
    __syncthreads();
    if (t < 8) {
        int v = ws[t];
        #pragma unroll
        for (int o = 4; o > 0; o >>= 1)
            v += __shfl_xor_sync(0xFFu, v, o);
        if (t == 0) g_bsum[blockIdx.x] = v;
    }
}

// ---------------- K3b: per-block rescan (folds block-sum scan in) --------------
__global__ void k_scan3(int N, int nb) {
    int t = threadIdx.x;
    int lane = t & 31, wid = t >> 5;
    __shared__ int s_pref;

    if (wid == 0) {
        int acc = 0;
        for (int i = lane; i < blockIdx.x; i += 32) acc += g_bsum[i];
        #pragma unroll
        for (int o = 16; o > 0; o >>= 1)
            acc += __shfl_xor_sync(0xFFFFFFFFu, acc, o);
        if (lane == 0) s_pref = acc;
    }
    if (blockIdx.x == 0 && wid == 1) {
        int acc = 0;
        for (int i = lane; i < nb; i += 32) acc += g_bsum[i];
        #pragma unroll
        for (int o = 16; o > 0; o >>= 1)
            acc += __shfl_xor_sync(0xFFFFFFFFu, acc, o);
        if (lane == 0) g_rowptr[N] = acc;
    }

    int base = blockIdx.x * SCAN_TILE + t * 4;
    int4 d = make_int4(0, 0, 0, 0);
    if (base + 3 < N) {
        d = *(const int4*)&g_deg[base];
    } else {
        if (base + 0 < N) d.x = g_deg[base + 0];
        if (base + 1 < N) d.y = g_deg[base + 1];
        if (base + 2 < N) d.z = g_deg[base + 2];
    }
    int s = d.x + d.y + d.z + d.w;
    int v = s;
    #pragma unroll
    for (int o = 1; o < 32; o <<= 1) {
        int u = __shfl_up_sync(0xFFFFFFFFu, v, o);
        if (lane >= o) v += u;
    }
    __shared__ int ws[8];
    if (lane == 31) ws[wid] = v;
    __syncthreads();
    if (wid == 0) {
        int w = (lane < 8) ? ws[lane] : 0;
        #pragma unroll
        for (int o = 1; o < 8; o <<= 1) {
            int u = __shfl_up_sync(0xFFFFFFFFu, w, o);
            if (lane >= o) w += u;
        }
        if (lane < 8) ws[lane] = w;
    }
    __syncthreads();
    int off = v - s + (wid > 0 ? ws[wid - 1] : 0) + s_pref;

    if (base + 3 < N) {
        int4 r = make_int4(off, off + d.x, off + d.x + d.y, off + d.x + d.y + d.z);
        *(int4*)&g_rowptr[base] = r;
        *(int4*)&g_cursor[base] = r;
    } else {
        int o0 = off;
        if (base + 0 < N) { g_rowptr[base + 0] = o0; g_cursor[base + 0] = o0; o0 += d.x; }
        if (base + 1 < N) { g_rowptr[base + 1] = o0; g_cursor[base + 1] = o0; o0 += d.y; }
        if (base + 2 < N) { g_rowptr[base + 2] = o0; g_cursor[base + 2] = o0; o0 += d.z; }
    }
}

// ---------------- K4: CSR scatter of {dst*32, t[dst]} (2 edges/thread) ---------
__global__ void k_edge(const void* __restrict__ ei, int E, int N) {
    __shared__ int s_is64;
    int is64 = probe_is64(ei, N, &s_is64);
    int e0 = (blockIdx.x * blockDim.x + threadIdx.x) * 2;
    if (e0 >= E) return;
    int s0, d0, s1 = -1, d1 = 0;
    if (is64) {
        const long long* p = (const long long*)ei;
        if (e0 + 1 < E) {
            longlong2 sv = *(const longlong2*)&p[e0];
            longlong2 dv = *(const longlong2*)&p[E + e0];
            s0 = (int)sv.x; s1 = (int)sv.y; d0 = (int)dv.x; d1 = (int)dv.y;
        } else { s0 = (int)p[e0]; d0 = (int)p[E + e0]; }
    } else {
        const int* p = (const int*)ei;
        if (e0 + 1 < E) {
            int2 sv = *(const int2*)&p[e0];
            int2 dv = *(const int2*)&p[E + e0];
            s0 = sv.x; s1 = sv.y; d0 = dv.x; d1 = dv.y;
        } else { s0 = p[e0]; d0 = p[E + e0]; }
    }
    float t0 = g_t[d0];
    int pos0 = atomicAdd(&g_cursor[s0], 1);
    g_pair[pos0] = make_int2(d0 << 5, __float_as_int(t0));
    if (s1 >= 0) {
        float t1 = g_t[d1];
        int pos1 = atomicAdd(&g_cursor[s1], 1);
        g_pair[pos1] = make_int2(d1 << 5, __float_as_int(t1));
    }
}

// ---------------- K5: per-node aggregation, MLP=4 unrolled gathers -------------
__global__ void k_agg(float* __restrict__ out, int N) {
    int node = (blockIdx.x * blockDim.x + threadIdx.x) >> 5;
    int lane = threadIdx.x & 31;
    if (node >= N) return;

    int start = g_rowptr[node];
    int end   = g_rowptr[node + 1];
    float s_row = g_s[node];
    if (lane == 0) g_deg[node] = 0;   // restore invariant for next replay

    const uint2* __restrict__ hv_base = (const uint2*)g_h;

    float4 acc = make_float4(0.f, 0.f, 0.f, 0.f);
    float rs = 0.f;

    for (int base = start; base < end; base += 32) {
        int n = min(32, end - base);
        int d = 0; float w = 0.f;
        if (lane < n) {
            int2 pr = g_pair[base + lane];
            d = pr.x;                                  // dst*32
            float val = s_row + __int_as_float(pr.y);
            float ea = val > 0.f ? val : ALPHA * val;
            w = __expf(ea);
        }
        int j = 0;
        for (; j + 4 <= n; j += 4) {
            int d0 = __shfl_sync(0xFFFFFFFFu, d, j);
            int d1 = __shfl_sync(0xFFFFFFFFu, d, j + 1);
            int d2 = __shfl_sync(0xFFFFFFFFu, d, j + 2);
            int d3 = __shfl_sync(0xFFFFFFFFu, d, j + 3);
            float w0 = __shfl_sync(0xFFFFFFFFu, w, j);
            float w1 = __shfl_sync(0xFFFFFFFFu, w, j + 1);
            float w2 = __shfl_sync(0xFFFFFFFFu, w, j + 2);
            float w3 = __shfl_sync(0xFFFFFFFFu, w, j + 3);
            uint2 v0 = hv_base[d0 + lane];
            uint2 v1 = hv_base[d1 + lane];
            uint2 v2 = hv_base[d2 + lane];
            uint2 v3 = hv_base[d3 + lane];
            float2 a0 = __half22float2(*(const __half2*)&v0.x);
            float2 b0 = __half22float2(*(const __half2*)&v0.y);
            acc.x = fmaf(w0, a0.x, acc.x); acc.y = fmaf(w0, a0.y, acc.y);
            acc.z = fmaf(w0, b0.x, acc.z); acc.w = fmaf(w0, b0.y, acc.w);
            float2 a1 = __half22float2(*(const __half2*)&v1.x);
            float2 b1 = __half22float2(*(const __half2*)&v1.y);
            acc.x = fmaf(w1, a1.x, acc.x); acc.y = fmaf(w1, a1.y, acc.y);
            acc.z = fmaf(w1, b1.x, acc.z); acc.w = fmaf(w1, b1.y, acc.w);
            float2 a2 = __half22float2(*(const __half2*)&v2.x);
            float2 b2 = __half22float2(*(const __half2*)&v2.y);
            acc.x = fmaf(w2, a2.x, acc.x); acc.y = fmaf(w2, a2.y, acc.y);
            acc.z = fmaf(w2, b2.x, acc.z); acc.w = fmaf(w2, b2.y, acc.w);
            float2 a3 = __half22float2(*(const __half2*)&v3.x);
            float2 b3 = __half22float2(*(const __half2*)&v3.y);
            acc.x = fmaf(w3, a3.x, acc.x); acc.y = fmaf(w3, a3.y, acc.y);
            acc.z = fmaf(w3, b3.x, acc.z); acc.w = fmaf(w3, b3.y, acc.w);
            rs += (w0 + w1) + (w2 + w3);
        }
        for (; j < n; j++) {
            int   dj = __shfl_sync(0xFFFFFFFFu, d, j);
            float wj = __shfl_sync(0xFFFFFFFFu, w, j);
            uint2 hv = hv_base[dj + lane];
            float2 f0 = __half22float2(*(const __half2*)&hv.x);
            float2 f1 = __half22float2(*(const __half2*)&hv.y);
            acc.x = fmaf(wj, f0.x, acc.x);
            acc.y = fmaf(wj, f0.y, acc.y);
            acc.z = fmaf(wj, f1.x, acc.z);
            acc.w = fmaf(wj, f1.y, acc.w);
            rs += wj;
        }
    }

    float inv = 1.f / (rs + EPS_GAT);
    float4 o;
    float vx = acc.x * inv, vy = acc.y * inv, vz = acc.z * inv, vw = acc.w * inv;
    o.x = vx > 0.f ? vx : expm1f(vx);
    o.y = vy > 0.f ? vy : expm1f(vy);
    o.z = vz > 0.f ? vz : expm1f(vz);
    o.w = vw > 0.f ? vw : expm1f(vw);
    ((float4*)out)[node * 32 + lane] = o;
}

// ---------------- launch ---------------------------------------------------------
extern "C" void kernel_launch(void* const* d_in, const int* in_sizes, int n_in,
                              void* d_out, int out_size) {
    const float* x    = (const float*)d_in[0];
    const void*  ei   = (const void*) d_in[1];
    const float* W    = (const float*)d_in[2];
    const float* attn = (const float*)d_in[3];
    float* out = (float*)d_out;

    int N = in_sizes[0] / IN_DIM;
    int E = in_sizes[1] / 2;
    int nb = (N + SCAN_TILE - 1) / SCAN_TILE;
    int nt = (N + 127) / 128;
    int ne2 = (E + 511) / 512;   // 2 edges per thread, 256 threads

    static cudaStream_t s2 = nullptr;
    static cudaEvent_t ev_fork = nullptr, ev_join = nullptr;
    if (!s2) {
        cudaStreamCreateWithFlags(&s2, cudaStreamNonBlocking);
        cudaEventCreateWithFlags(&ev_fork, cudaEventDisableTiming);
        cudaEventCreateWithFlags(&ev_join, cudaEventDisableTiming);
        cudaFuncSetAttribute(k_gemm_mma, cudaFuncAttributeMaxDynamicSharedMemorySize, SM_TOT);
    }

    // fork: GEMM overlaps hist+scan chain
    cudaEventRecord(ev_fork, 0);
    cudaStreamWaitEvent(s2, ev_fork, 0);
    k_gemm_mma<<<nt, 256, SM_TOT, s2>>>(x, W, attn, N);
    cudaEventRecord(ev_join, s2);

    k_hist <<<ne2, 256>>>(ei, E, N);
    k_scan1<<<nb, 256>>>(N);
    k_scan3<<<nb, 256>>>(N, nb);

    // k_edge needs g_t (GEMM) + g_cursor (scan3)
    cudaStreamWaitEvent(0, ev_join, 0);
    k_edge <<<ne2, 256>>>(ei, E, N);
    k_agg  <<<((long long)N * 32 + 255) / 256, 256>>>(out, N);
}

// round 9
// speedup vs baseline: 1.0293x; 1.0293x over previous
#include <cuda_runtime.h>
#include <cuda_fp16.h>
#include <math.h>
#include <stdint.h>

#define IN_DIM   128
#define OUT_DIM  128
#define CAP_N    100000
#define CAP_E    1600000
#define ALPHA    0.2f
#define EPS_GAT  9e-15f
#define SCAN_TILE 1024
#define MAX_SCAN_BLOCKS 1024

// ---------------- scratch (static __device__, zero-initialized) ---------------
__device__ __half g_h[CAP_N * OUT_DIM];    // 25.6 MB, fp16 h for gathers
__device__ float g_s[CAP_N];
__device__ float g_t[CAP_N];
__device__ int   g_deg[CAP_N];             // zero at load; re-zeroed by k_agg
__device__ int   g_rowptr[CAP_N + 1];
__device__ int   g_cursor[CAP_N];
__device__ int   g_dst[CAP_E];             // CSR payload: dst
__device__ unsigned g_state[MAX_SCAN_BLOCKS]; // lookback state; re-zeroed by k_agg

// ---------------- helpers ------------------------------------------------------
__device__ __forceinline__ uint32_t smem_u32(const void* p) {
    uint32_t a;
    asm("{ .reg .u64 t; cvta.to.shared.u64 t, %1; cvt.u32.u64 %0, t; }"
        : "=r"(a) : "l"(p));
    return a;
}
__device__ __forceinline__ int probe_is64(const void* ei, int N, int* s_flag) {
    if (threadIdx.x < 32) {
        long long v = ((const long long*)ei)[threadIdx.x];
        int bad = (v < 0 || v >= (long long)N) ? 1 : 0;
        unsigned m = __ballot_sync(0xFFFFFFFFu, bad);
        if (threadIdx.x == 0) *s_flag = (m == 0);
    }
    __syncthreads();
    return *s_flag;
}

// ---------------- K1: mma.sync GEMM: h = x @ W (fp16 in, fp32 acc) ------------
#define XS 136
#define SM_XS   0
#define SM_WS   34816
#define SM_ATTN 69632
#define SM_TOT  70656

__global__ void __launch_bounds__(256)
k_gemm_mma(const float* __restrict__ x, const float* __restrict__ W,
           const float* __restrict__ attn, int N) {
    extern __shared__ char sm[];
    __half* xs = (__half*)(sm + SM_XS);
    __half* ws = (__half*)(sm + SM_WS);
    float* s_attn = (float*)(sm + SM_ATTN);

    const int tid = threadIdx.x;
    const int wid = tid >> 5;
    const int lane = tid & 31;
    const int row0 = blockIdx.x * 128;

    s_attn[tid] = attn[tid];

    #pragma unroll
    for (int it = 0; it < 16; it++) {
        int idx = it * 256 + tid;
        int r = idx >> 5, c4 = (idx & 31) * 4;
        int gr = row0 + r;
        float4 v = make_float4(0.f, 0.f, 0.f, 0.f);
        if (gr < N) v = ((const float4*)x)[(long long)gr * 32 + (idx & 31)];
        __half2 h0 = __float22half2_rn(make_float2(v.x, v.y));
        __half2 h1 = __float22half2_rn(make_float2(v.z, v.w));
        *(uint2*)&xs[r * XS + c4] = make_uint2(*(unsigned*)&h0, *(unsigned*)&h1);
    }
    #pragma unroll
    for (int it = 0; it < 16; it++) {
        int idx = it * 256 + tid;
        int k = idx >> 5, c4 = (idx & 31) * 4;
        float4 v = ((const float4*)W)[idx];
        __half2 h0 = __float22half2_rn(make_float2(v.x, v.y));
        __half2 h1 = __float22half2_rn(make_float2(v.z, v.w));
        *(uint2*)&ws[k * XS + c4] = make_uint2(*(unsigned*)&h0, *(unsigned*)&h1);
    }
    __syncthreads();

    const uint32_t xs_b = smem_u32(xs);
    const uint32_t ws_b = smem_u32(ws);
    const int r0 = wid * 16;
    const int rl = r0 + (lane >> 2);
    const int rh = rl + 8;
    float p_lo = 0.f, q_lo = 0.f, p_hi = 0.f, q_hi = 0.f;

    #pragma unroll
    for (int half = 0; half < 2; half++) {
        float c[8][4];
        #pragma unroll
        for (int t = 0; t < 8; t++)
            c[t][0] = c[t][1] = c[t][2] = c[t][3] = 0.f;

        #pragma unroll
        for (int k0 = 0; k0 < 8; k0++) {
            int k = k0 * 16;
            int g = lane >> 3;
            int arow = r0 + (lane & 7) + (g & 1) * 8;
            int acol = k + (g >> 1) * 8;
            uint32_t aaddr = xs_b + (arow * XS + acol) * 2;
            uint32_t a0, a1, a2, a3;
            asm volatile("ldmatrix.sync.aligned.m8n8.x4.shared.b16 {%0,%1,%2,%3}, [%4];"
                         : "=r"(a0), "=r"(a1), "=r"(a2), "=r"(a3) : "r"(aaddr));
            #pragma unroll
            for (int t = 0; t < 8; t++) {
                int n0 = half * 64 + t * 8;
                int brow = k + (lane & 15);
                uint32_t baddr = ws_b + (brow * XS + n0) * 2;
                uint32_t b0, b1;
                asm volatile("ldmatrix.sync.aligned.m8n8.x2.trans.shared.b16 {%0,%1}, [%2];"
                             : "=r"(b0), "=r"(b1) : "r"(baddr));
                asm volatile(
                    "mma.sync.aligned.m16n8k16.row.col.f32.f16.f16.f32 "
                    "{%0,%1,%2,%3}, {%4,%5,%6,%7}, {%8,%9}, {%0,%1,%2,%3};"
                    : "+f"(c[t][0]), "+f"(c[t][1]), "+f"(c[t][2]), "+f"(c[t][3])
                    : "r"(a0), "r"(a1), "r"(a2), "r"(a3), "r"(b0), "r"(b1));
            }
        }
        #pragma unroll
        for (int t = 0; t < 8; t++) {
            int col0 = half * 64 + t * 8 + (lane & 3) * 2;
            float as0 = s_attn[col0], as1 = s_attn[col0 + 1];
            float ad0 = s_attn[128 + col0], ad1 = s_attn[128 + col0 + 1];
            p_lo = fmaf(c[t][0], as0, fmaf(c[t][1], as1, p_lo));
            q_lo = fmaf(c[t][0], ad0, fmaf(c[t][1], ad1, q_lo));
            p_hi = fmaf(c[t][2], as0, fmaf(c[t][3], as1, p_hi));
            q_hi = fmaf(c[t][2], ad0, fmaf(c[t][3], ad1, q_hi));
            __half2 hl = __float22half2_rn(make_float2(c[t][0], c[t][1]));
            __half2 hh = __float22half2_rn(make_float2(c[t][2], c[t][3]));
            if (row0 + rl < N) *(__half2*)&g_h[(long long)(row0 + rl) * 128 + col0] = hl;
            if (row0 + rh < N) *(__half2*)&g_h[(long long)(row0 + rh) * 128 + col0] = hh;
        }
    }
    #pragma unroll
    for (int o = 1; o <= 2; o <<= 1) {
        p_lo += __shfl_xor_sync(0xFFFFFFFFu, p_lo, o);
        q_lo += __shfl_xor_sync(0xFFFFFFFFu, q_lo, o);
        p_hi += __shfl_xor_sync(0xFFFFFFFFu, p_hi, o);
        q_hi += __shfl_xor_sync(0xFFFFFFFFu, q_hi, o);
    }
    if ((lane & 3) == 0) {
        if (row0 + rl < N) { g_s[row0 + rl] = p_lo; g_t[row0 + rl] = q_lo; }
        if (row0 + rh < N) { g_s[row0 + rh] = p_hi; g_t[row0 + rh] = q_hi; }
    }
}

// ---------------- K2: histogram of src ----------------------------------------
__global__ void k_hist(const void* __restrict__ ei, int E, int N) {
    __shared__ int s_is64;
    int is64 = probe_is64(ei, N, &s_is64);
    int e = blockIdx.x * blockDim.x + threadIdx.x;
    if (e >= E) return;
    int s;
    if (is64) s = (int)((const long long*)ei)[e];
    else      s = ((const int*)ei)[e];
    atomicAdd(&g_deg[s], 1);
}

// ---------------- K3: single-pass scan with decoupled lookback -----------------
// flag in bits[31:30]: 0=empty, 1=partial(block sum), 2=prefix(inclusive)
__global__ void k_scan(int N, int nb) {
    const int t = threadIdx.x;
    const int lane = t & 31, wid = t >> 5;
    const int b = blockIdx.x;

    int base = b * SCAN_TILE + t * 4;
    int4 d = make_int4(0, 0, 0, 0);
    if (base + 3 < N) {
        d = *(const int4*)&g_deg[base];
    } else {
        if (base + 0 < N) d.x = g_deg[base + 0];
        if (base + 1 < N) d.y = g_deg[base + 1];
        if (base + 2 < N) d.z = g_deg[base + 2];
    }
    int s = d.x + d.y + d.z + d.w;

    // intra-warp inclusive scan
    int v = s;
    #pragma unroll
    for (int o = 1; o < 32; o <<= 1) {
        int u = __shfl_up_sync(0xFFFFFFFFu, v, o);
        if (lane >= o) v += u;
    }
    __shared__ int ws[8];
    if (lane == 31) ws[wid] = v;
    __syncthreads();
    if (wid == 0) {
        int w = (lane < 8) ? ws[lane] : 0;
        #pragma unroll
        for (int o = 1; o < 8; o <<= 1) {
            int u = __shfl_up_sync(0xFFFFFFFFu, w, o);
            if (lane >= o) w += u;
        }
        if (lane < 8) ws[lane] = w;
    }
    __syncthreads();

    // lookback (thread 0)
    __shared__ int s_prefix;
    if (t == 0) {
        int S = ws[7];  // block total
        if (b == 0) {
            atomicExch(&g_state[0], (2u << 30) | (unsigned)S);
            s_prefix = 0;
            if (nb == 1) g_rowptr[N] = S;
        } else {
            atomicExch(&g_state[b], (1u << 30) | (unsigned)S);
            int ex = 0;
            int i = b - 1;
            while (true) {
                unsigned st = atomicAdd(&g_state[i], 0u);
                unsigned f = st >> 30;
                if (f == 0) continue;
                ex += (int)(st & 0x3FFFFFFFu);
                if (f == 2u) break;
                i--;
            }
            atomicExch(&g_state[b], (2u << 30) | (unsigned)(ex + S));
            s_prefix = ex;
            if (b == nb - 1) g_rowptr[N] = ex + S;
        }
    }
    __syncthreads();

    int off = v - s + (wid > 0 ? ws[wid - 1] : 0) + s_prefix;

    if (base + 3 < N) {
        int4 r = make_int4(off, off + d.x, off + d.x + d.y, off + d.x + d.y + d.z);
        *(int4*)&g_rowptr[base] = r;
        *(int4*)&g_cursor[base] = r;
    } else {
        int o0 = off;
        if (base + 0 < N) { g_rowptr[base + 0] = o0; g_cursor[base + 0] = o0; o0 += d.x; }
        if (base + 1 < N) { g_rowptr[base + 1] = o0; g_cursor[base + 1] = o0; o0 += d.y; }
        if (base + 2 < N) { g_rowptr[base + 2] = o0; g_cursor[base + 2] = o0; o0 += d.z; }
    }
}

// ---------------- K4: CSR scatter (dst only; no GEMM dependency) ---------------
__global__ void k_edge(const void* __restrict__ ei, int E, int N) {
    __shared__ int s_is64;
    int is64 = probe_is64(ei, N, &s_is64);
    int e = blockIdx.x * blockDim.x + threadIdx.x;
    if (e >= E) return;
    int s, d;
    if (is64) {
        const long long* p = (const long long*)ei;
        s = (int)p[e]; d = (int)p[E + e];
    } else {
        const int* p = (const int*)ei;
        s = p[e]; d = p[E + e];
    }
    int pos = atomicAdd(&g_cursor[s], 1);
    g_dst[pos] = d;
}

// ---------------- K5: per-node aggregation (softmax weight inline) -------------
__global__ void k_agg(float* __restrict__ out, int N) {
    int node = (blockIdx.x * blockDim.x + threadIdx.x) >> 5;
    int lane = threadIdx.x & 31;
    if (node >= N) return;

    int start = g_rowptr[node];
    int end   = g_rowptr[node + 1];
    float s_row = g_s[node];
    // restore replay invariants
    if (lane == 1) g_deg[node] = 0;
    if (lane == 2 && node < MAX_SCAN_BLOCKS) g_state[node] = 0;

    float4 acc = make_float4(0.f, 0.f, 0.f, 0.f);
    float rs = 0.f;

    for (int base = start; base < end; base += 32) {
        int n = min(32, end - base);
        int d = 0; float w = 0.f;
        if (lane < n) {
            d = g_dst[base + lane];
            float val = s_row + g_t[d];
            float ea = val > 0.f ? val : ALPHA * val;
            w = __expf(ea);
        }
        for (int j = 0; j < n; j++) {
            int   dj = __shfl_sync(0xFFFFFFFFu, d, j);
            float wj = __shfl_sync(0xFFFFFFFFu, w, j);
            uint2 hv = ((const uint2*)g_h)[dj * 32 + lane];
            float2 f0 = __half22float2(*(const __half2*)&hv.x);
            float2 f1 = __half22float2(*(const __half2*)&hv.y);
            acc.x = fmaf(wj, f0.x, acc.x);
            acc.y = fmaf(wj, f0.y, acc.y);
            acc.z = fmaf(wj, f1.x, acc.z);
            acc.w = fmaf(wj, f1.y, acc.w);
            rs += wj;
        }
    }

    float inv = 1.f / (rs + EPS_GAT);
    float4 o;
    float vx = acc.x * inv, vy = acc.y * inv, vz = acc.z * inv, vw = acc.w * inv;
    o.x = vx > 0.f ? vx : expm1f(vx);
    o.y = vy > 0.f ? vy : expm1f(vy);
    o.z = vz > 0.f ? vz : expm1f(vz);
    o.w = vw > 0.f ? vw : expm1f(vw);
    ((float4*)out)[node * 32 + lane] = o;
}

// ---------------- launch ---------------------------------------------------------
extern "C" void kernel_launch(void* const* d_in, const int* in_sizes, int n_in,
                              void* d_out, int out_size) {
    const float* x    = (const float*)d_in[0];
    const void*  ei   = (const void*) d_in[1];
    const float* W    = (const float*)d_in[2];
    const float* attn = (const float*)d_in[3];
    float* out = (float*)d_out;

    int N = in_sizes[0] / IN_DIM;
    int E = in_sizes[1] / 2;
    int nb = (N + SCAN_TILE - 1) / SCAN_TILE;
    int nt = (N + 127) / 128;

    static cudaStream_t s2 = nullptr;
    static cudaEvent_t ev_fork = nullptr, ev_join = nullptr;
    if (!s2) {
        cudaStreamCreateWithFlags(&s2, cudaStreamNonBlocking);
        cudaEventCreateWithFlags(&ev_fork, cudaEventDisableTiming);
        cudaEventCreateWithFlags(&ev_join, cudaEventDisableTiming);
        cudaFuncSetAttribute(k_gemm_mma, cudaFuncAttributeMaxDynamicSharedMemorySize, SM_TOT);
    }

    // fork: GEMM overlaps the whole hist+scan+edge chain
    cudaEventRecord(ev_fork, 0);
    cudaStreamWaitEvent(s2, ev_fork, 0);
    k_gemm_mma<<<nt, 256, SM_TOT, s2>>>(x, W, attn, N);
    cudaEventRecord(ev_join, s2);

    k_hist<<<(E + 255) / 256, 256>>>(ei, E, N);
    k_scan<<<nb, 256>>>(N, nb);
    k_edge<<<(E + 255) / 256, 256>>>(ei, E, N);

    // join: aggregation needs g_h, g_s, g_t from the GEMM
    cudaStreamWaitEvent(0, ev_join, 0);
    k_agg <<<((long long)N * 32 + 255) / 256, 256>>>(out, N);
}